// round 5
// baseline (speedup 1.0000x reference)
#include <cuda_runtime.h>
#include <cuda_bf16.h>

// Soft_NN forward == exact 1-NN: out[b,n,:] = y_c[b, argmin_m dist(x[b,n], y[b,m]), :]
//   dist = x2 + y2 - 2*x.y, computed in strict fp32 to track the reference's rounding.
// Shapes: B=4, N=4096, M=4096, C=32. Inputs: x_f, y_f, y_c, temp_inv (unused, >0).

#define B_  4
#define N_  4096
#define M_  4096
#define C_  32
#define BN  128          // queries per CTA
#define BM  128          // candidates per chunk
#define TN  8            // queries per thread
#define TM  8            // candidates per thread
#define SSTR 132         // padded smem stride (floats), 132 % 4 == 0 for float4

__global__ __launch_bounds__(256, 1)
void soft_nn_kernel(const float* __restrict__ x,
                    const float* __restrict__ y,
                    const float* __restrict__ yc,
                    float* __restrict__ out)
{
    __shared__ float Xs[C_][SSTR];   // transposed: Xs[k][n]
    __shared__ float Ys[C_][SSTR];   // transposed: Ys[k][m]
    __shared__ float x2s[BN];
    __shared__ float y2s[BM];

    const int tid = threadIdx.x;
    const int tx  = tid & 15;        // 16 m-lanes
    const int ty  = tid >> 4;        // 16 n-lanes
    const int blk = blockIdx.x;      // 0..127
    const int b   = blk >> 5;        // 32 CTAs per batch
    const int n0  = (blk & 31) * BN;

    const float4* xg = (const float4*)(x + ((size_t)b * N_ + n0) * C_);
    const float4* yg = (const float4*)(y + (size_t)b * M_ * C_);

    // ---- load X tile [BN x C] transposed into Xs[C][BN] ----
    #pragma unroll
    for (int t = tid; t < BN * C_ / 4; t += 256) {
        int n  = t >> 3;             // 8 float4 per row (C=32)
        int c4 = (t & 7) << 2;
        float4 v = xg[t];
        Xs[c4 + 0][n] = v.x;
        Xs[c4 + 1][n] = v.y;
        Xs[c4 + 2][n] = v.z;
        Xs[c4 + 3][n] = v.w;
    }
    __syncthreads();
    if (tid < BN) {
        float s = 0.f;
        #pragma unroll
        for (int k = 0; k < C_; k++) { float v = Xs[k][tid]; s = fmaf(v, v, s); }
        x2s[tid] = s;
    }

    float bestd[TN];
    int   bestm[TN];
    #pragma unroll
    for (int i = 0; i < TN; i++) { bestd[i] = 3.4e38f; bestm[i] = 0; }

    for (int mc = 0; mc < M_; mc += BM) {
        __syncthreads();  // protect Ys/y2s reuse across chunks (also covers x2s first use)

        // ---- load Y chunk [BM x C] transposed into Ys[C][BM] ----
        const float4* ygc = yg + (mc * C_) / 4;
        #pragma unroll
        for (int t = tid; t < BM * C_ / 4; t += 256) {
            int m  = t >> 3;
            int c4 = (t & 7) << 2;
            float4 v = ygc[t];
            Ys[c4 + 0][m] = v.x;
            Ys[c4 + 1][m] = v.y;
            Ys[c4 + 2][m] = v.z;
            Ys[c4 + 3][m] = v.w;
        }
        __syncthreads();
        if (tid < BM) {
            float s = 0.f;
            #pragma unroll
            for (int k = 0; k < C_; k++) { float v = Ys[k][tid]; s = fmaf(v, v, s); }
            y2s[tid] = s;
        }
        __syncthreads();

        // ---- 8x8 register tile: s[i][j] = x[n].y[m] over k=0..31 ----
        float acc[TN][TM];
        #pragma unroll
        for (int i = 0; i < TN; i++)
            #pragma unroll
            for (int j = 0; j < TM; j++) acc[i][j] = 0.f;

        #pragma unroll
        for (int k = 0; k < C_; k++) {
            float4 xa = *(const float4*)&Xs[k][ty * TN];
            float4 xb = *(const float4*)&Xs[k][ty * TN + 4];
            float4 ya = *(const float4*)&Ys[k][tx * TM];
            float4 yb = *(const float4*)&Ys[k][tx * TM + 4];
            float xr[8] = {xa.x, xa.y, xa.z, xa.w, xb.x, xb.y, xb.z, xb.w};
            float yr[8] = {ya.x, ya.y, ya.z, ya.w, yb.x, yb.y, yb.z, yb.w};
            #pragma unroll
            for (int i = 0; i < TN; i++)
                #pragma unroll
                for (int j = 0; j < TM; j++)
                    acc[i][j] = fmaf(xr[i], yr[j], acc[i][j]);
        }

        // ---- argmin update (reference rounding: (x2+y2) - (2*s)) ----
        #pragma unroll
        for (int i = 0; i < TN; i++) {
            float x2 = x2s[ty * TN + i];
            #pragma unroll
            for (int j = 0; j < TM; j++) {
                float d = __fsub_rn(__fadd_rn(x2, y2s[tx * TM + j]),
                                    __fmul_rn(2.0f, acc[i][j]));
                int m = mc + tx * TM + j;
                // strict < keeps the earliest m on exact ties (j and mc both ascend)
                if (d < bestd[i]) { bestd[i] = d; bestm[i] = m; }
            }
        }
    }

    // ---- cross-tx reduction (reuse smem tiles as scratch) ----
    __syncthreads();
    float* redD = &Ys[0][0];         // BN*16 = 2048 floats
    int*   redM = (int*)&Xs[0][0];   // 2048 ints
    #pragma unroll
    for (int i = 0; i < TN; i++) {
        int n = ty * TN + i;
        redD[n * 16 + tx] = bestd[i];
        redM[n * 16 + tx] = bestm[i];
    }
    __syncthreads();
    if (tid < BN) {
        float bd = redD[tid * 16];
        int   bm = redM[tid * 16];
        #pragma unroll
        for (int t = 1; t < 16; t++) {
            float d = redD[tid * 16 + t];
            int   m = redM[tid * 16 + t];
            if (d < bd || (d == bd && m < bm)) { bd = d; bm = m; }
        }
        const float* src = yc + ((size_t)b * M_ + bm) * 3;
        float*       dst = out + ((size_t)b * N_ + n0 + tid) * 3;
        dst[0] = src[0];
        dst[1] = src[1];
        dst[2] = src[2];
    }
}

extern "C" void kernel_launch(void* const* d_in, const int* in_sizes, int n_in,
                              void* d_out, int out_size)
{
    const float* x  = (const float*)d_in[0];   // x_f  [4,4096,32]
    const float* y  = (const float*)d_in[1];   // y_f  [4,4096,32]
    const float* yc = (const float*)d_in[2];   // y_c  [4,4096,3]
    // d_in[3] = temp_inv (positive constant; does not affect argmax)
    float* out = (float*)d_out;                // [4,4096,3]
    soft_nn_kernel<<<(B_ * N_) / BN, 256>>>(x, y, yc, out);
}

// round 7
// speedup vs baseline: 2.0068x; 2.0068x over previous
#include <cuda_runtime.h>
#include <cuda_bf16.h>

// Soft_NN forward == exact 1-NN: out[b,n,:] = y_c[b, argmin_m dist(x[b,n], y[b,m]), :]
//   dist = fl(fl(x2+y2) - 2*s), s = fp32 FMA dot product (same rounding as before:
//   2*s is exact, so fmaf(-2,s,x2+y2) == fsub(fadd(x2,y2), fmul(2,s)) bitwise).
// R5: FFMA2 (fma.rn.f32x2) packed math — 2 fp32 FMA per instruction (rt=2/SMSP),
//     conflict-free y-tile LDS mapping, register-prefetched Y chunks.

#define B_  4
#define N_  4096
#define M_  4096
#define C_  32
#define BN  128
#define BM  128
#define SSTR 132         // padded smem stride (floats); 132*4 bytes, 16B-aligned rows

typedef unsigned long long u64v;

__device__ __forceinline__ u64v pack2(float lo, float hi) {
    u64v r;
    asm("mov.b64 %0, {%1, %2};" : "=l"(r)
        : "r"(__float_as_uint(lo)), "r"(__float_as_uint(hi)));
    return r;
}
__device__ __forceinline__ u64v fma2(u64v a, u64v b, u64v c) {
    u64v d;
    asm("fma.rn.f32x2 %0, %1, %2, %3;" : "=l"(d) : "l"(a), "l"(b), "l"(c));
    return d;
}
__device__ __forceinline__ void unpack2(u64v v, float& lo, float& hi) {
    unsigned ulo, uhi;
    asm("mov.b64 {%0, %1}, %2;" : "=r"(ulo), "=r"(uhi) : "l"(v));
    lo = __uint_as_float(ulo);
    hi = __uint_as_float(uhi);
}

__global__ __launch_bounds__(256, 1)
void soft_nn_kernel(const float* __restrict__ x,
                    const float* __restrict__ y,
                    const float* __restrict__ yc,
                    float* __restrict__ out)
{
    __shared__ __align__(16) float Xs[C_][SSTR];   // transposed: Xs[k][n]
    __shared__ __align__(16) float Ys[C_][SSTR];   // transposed: Ys[k][m]
    __shared__ float x2s[BN];
    __shared__ float y2s[BM];

    const int tid = threadIdx.x;
    const int tx  = tid & 15;        // 16 m-lanes
    const int ty  = tid >> 4;        // 16 n-lanes
    const int blk = blockIdx.x;      // 0..127
    const int b   = blk >> 5;        // 32 CTAs per batch
    const int n0  = (blk & 31) * BN;

    const float4* xg = (const float4*)(x + ((size_t)b * N_ + n0) * C_);
    const float4* yg = (const float4*)(y + (size_t)b * M_ * C_);

    // ---- load X tile [BN x C] transposed into Xs[C][BN] ----
    #pragma unroll
    for (int t = tid; t < BN * C_ / 4; t += 256) {
        int n  = t >> 3;             // 8 float4 per row (C=32)
        int c4 = (t & 7) << 2;
        float4 v = xg[t];
        Xs[c4 + 0][n] = v.x;
        Xs[c4 + 1][n] = v.y;
        Xs[c4 + 2][n] = v.z;
        Xs[c4 + 3][n] = v.w;
    }
    __syncthreads();
    if (tid < BN) {
        float s = 0.f;
        #pragma unroll
        for (int k = 0; k < C_; k++) { float v = Xs[k][tid]; s = fmaf(v, v, s); }
        x2s[tid] = s;
    }
    __syncthreads();                 // x2s visible to all

    float x2r[8];
    #pragma unroll
    for (int i = 0; i < 8; i++) x2r[i] = x2s[ty * 8 + i];

    // ---- prefetch first Y chunk into registers ----
    float4 pf[4];
    #pragma unroll
    for (int r = 0; r < 4; r++) pf[r] = yg[tid + 256 * r];

    float bestd[8];
    int   bestm[8];
    #pragma unroll
    for (int i = 0; i < 8; i++) { bestd[i] = 3.4e38f; bestm[i] = 0; }

    for (int mc = 0; mc < M_; mc += BM) {
        __syncthreads();  // previous chunk's compute done reading Ys/y2s

        // ---- store prefetched Y chunk transposed into Ys[C][BM] ----
        #pragma unroll
        for (int r = 0; r < 4; r++) {
            int t  = tid + 256 * r;
            int m  = t >> 3;
            int c4 = (t & 7) << 2;
            float4 v = pf[r];
            Ys[c4 + 0][m] = v.x;
            Ys[c4 + 1][m] = v.y;
            Ys[c4 + 2][m] = v.z;
            Ys[c4 + 3][m] = v.w;
        }
        __syncthreads();
        if (tid < BM) {
            float s = 0.f;
            #pragma unroll
            for (int k = 0; k < C_; k++) { float v = Ys[k][tid]; s = fmaf(v, v, s); }
            y2s[tid] = s;
        }
        // issue next chunk's global loads (completes under the compute below)
        if (mc + BM < M_) {
            const float4* ygn = yg + ((mc + BM) * C_) / 4;
            #pragma unroll
            for (int r = 0; r < 4; r++) pf[r] = ygn[tid + 256 * r];
        }
        __syncthreads();  // y2s ready

        // ---- packed 8x8 register tile via FFMA2: pairs along queries (i) ----
        // thread's candidates: m = mc + tx*4 + j (j<4)  and  mc + 64 + tx*4 + (j-4)
        u64v acc[4][8];
        #pragma unroll
        for (int i2 = 0; i2 < 4; i2++)
            #pragma unroll
            for (int j = 0; j < 8; j++) acc[i2][j] = 0ULL;

        #pragma unroll 8
        for (int k = 0; k < C_; k++) {
            ulonglong2 xp = *(const ulonglong2*)&Xs[k][ty * 8];       // (x0,x1),(x2,x3)
            ulonglong2 xq = *(const ulonglong2*)&Xs[k][ty * 8 + 4];   // (x4,x5),(x6,x7)
            float4 ya = *(const float4*)&Ys[k][tx * 4];               // conflict-free
            float4 yb = *(const float4*)&Ys[k][64 + tx * 4];          // conflict-free
            u64v xpair[4] = { xp.x, xp.y, xq.x, xq.y };
            u64v yp[8] = {
                pack2(ya.x, ya.x), pack2(ya.y, ya.y), pack2(ya.z, ya.z), pack2(ya.w, ya.w),
                pack2(yb.x, yb.x), pack2(yb.y, yb.y), pack2(yb.z, yb.z), pack2(yb.w, yb.w)
            };
            #pragma unroll
            for (int i2 = 0; i2 < 4; i2++)
                #pragma unroll
                for (int j = 0; j < 8; j++)
                    acc[i2][j] = fma2(xpair[i2], yp[j], acc[i2][j]);
        }

        // ---- argmin update (reference rounding; 2*s exact => fmaf is identical) ----
        float yyr[8];
        int   mr[8];
        #pragma unroll
        for (int j = 0; j < 8; j++) {
            int mloc = (j < 4) ? (tx * 4 + j) : (64 + tx * 4 + (j - 4));
            yyr[j] = y2s[mloc];
            mr[j]  = mc + mloc;
        }
        #pragma unroll
        for (int i2 = 0; i2 < 4; i2++) {
            #pragma unroll
            for (int j = 0; j < 8; j++) {
                float slo, shi;
                unpack2(acc[i2][j], slo, shi);
                float dlo = fmaf(-2.0f, slo, __fadd_rn(x2r[2 * i2],     yyr[j]));
                float dhi = fmaf(-2.0f, shi, __fadd_rn(x2r[2 * i2 + 1], yyr[j]));
                // strict < keeps earliest m per thread (j and mc both ascend in m)
                if (dlo < bestd[2 * i2])     { bestd[2 * i2]     = dlo; bestm[2 * i2]     = mr[j]; }
                if (dhi < bestd[2 * i2 + 1]) { bestd[2 * i2 + 1] = dhi; bestm[2 * i2 + 1] = mr[j]; }
            }
        }
    }

    // ---- cross-tx reduction (reuse smem tiles as scratch) ----
    __syncthreads();
    float* redD = &Ys[0][0];         // BN*16 = 2048 floats
    int*   redM = (int*)&Xs[0][0];   // 2048 ints
    #pragma unroll
    for (int i = 0; i < 8; i++) {
        int n = ty * 8 + i;
        redD[n * 16 + tx] = bestd[i];
        redM[n * 16 + tx] = bestm[i];
    }
    __syncthreads();
    if (tid < BN) {
        float bd = redD[tid * 16];
        int   bm = redM[tid * 16];
        #pragma unroll
        for (int t = 1; t < 16; t++) {
            float d = redD[tid * 16 + t];
            int   m = redM[tid * 16 + t];
            if (d < bd || (d == bd && m < bm)) { bd = d; bm = m; }
        }
        const float* src = yc + ((size_t)b * M_ + bm) * 3;
        float*       dst = out + ((size_t)b * N_ + n0 + tid) * 3;
        dst[0] = src[0];
        dst[1] = src[1];
        dst[2] = src[2];
    }
}

extern "C" void kernel_launch(void* const* d_in, const int* in_sizes, int n_in,
                              void* d_out, int out_size)
{
    const float* x  = (const float*)d_in[0];   // x_f  [4,4096,32]
    const float* y  = (const float*)d_in[1];   // y_f  [4,4096,32]
    const float* yc = (const float*)d_in[2];   // y_c  [4,4096,3]
    // d_in[3] = temp_inv (positive constant; does not affect argmax)
    float* out = (float*)d_out;                // [4,4096,3]
    soft_nn_kernel<<<(B_ * N_) / BN, 256>>>(x, y, yc, out);
}